// round 2
// baseline (speedup 1.0000x reference)
#include <cuda_runtime.h>
#include <cstddef>

#define THREADS 256
#define WARPS   8
#define EPW     8                      // batch elements per warp
#define ROWS_PER_CTA (WARPS * EPW)     // 64
#define HDIM    32
#define WPAD    129                    // padded row stride (words) for conflict-free transposed weights
#define NEG_SLOPE 0.01f

__device__ __forceinline__ float sigm_f(float x) {
    // 1 / (1 + e^-x)  via MUFU.EX2 + MUFU.RCP (accurate to ~1e-6 rel)
    return __fdividef(1.0f, 1.0f + __expf(-x));
}
__device__ __forceinline__ float tanh_f(float x) {
    // 2/(1+e^-2x) - 1
    return __fdividef(2.0f, 1.0f + __expf(-2.0f * x)) - 1.0f;
}

// One matvec-accumulate pass: acc[t][e] += sum_k WT[k][t*32+lane] * M[e][k]
// WT is transposed-padded weights in shared, M is the warp-private source tile.
__device__ __forceinline__ void gate_pass(
    const float* __restrict__ sWT, const float* __restrict__ sMw, int lane,
    float (&ai)[EPW], float (&af)[EPW], float (&ag)[EPW], float (&ao)[EPW])
{
    #pragma unroll
    for (int k4 = 0; k4 < HDIM / 4; k4++) {
        float4 mv[EPW];
        #pragma unroll
        for (int e = 0; e < EPW; e++)
            mv[e] = reinterpret_cast<const float4*>(sMw)[e * (HDIM / 4) + k4];  // broadcast
        #pragma unroll
        for (int kk = 0; kk < 4; kk++) {
            const float* wrow = sWT + (size_t)(k4 * 4 + kk) * WPAD;
            float wi = wrow[lane];
            float wf = wrow[32 + lane];
            float wg = wrow[64 + lane];
            float wo = wrow[96 + lane];
            #pragma unroll
            for (int e = 0; e < EPW; e++) {
                float m = (kk == 0) ? mv[e].x : (kk == 1) ? mv[e].y
                        : (kk == 2) ? mv[e].z : mv[e].w;
                ai[e] = fmaf(wi, m, ai[e]);
                af[e] = fmaf(wf, m, af[e]);
                ag[e] = fmaf(wg, m, ag[e]);
                ao[e] = fmaf(wo, m, ao[e]);
            }
        }
    }
}

__global__ __launch_bounds__(THREADS)
void lstm4_kernel(const float* __restrict__ x,
                  const float* __restrict__ h0,
                  const float* __restrict__ c0,
                  const float* __restrict__ Wih,
                  const float* __restrict__ Whh,
                  const float* __restrict__ bih,
                  const float* __restrict__ bhh,
                  float* __restrict__ out, int n)
{
    __shared__ float sWih[HDIM * WPAD];            // transposed: sWih[k*WPAD + g]
    __shared__ float sWhh[HDIM * WPAD];
    __shared__ float sM[WARPS * EPW * HDIM];       // per-warp source tile (x, then h)

    const int tid  = threadIdx.x;
    const int lane = tid & 31;
    const int w    = tid >> 5;

    // ---- cooperative transpose-load of both weight matrices (broadcast-friendly, conflict-free) ----
    for (int i = tid; i < 4 * HDIM * HDIM; i += THREADS) {   // 4096 each
        int g = i >> 5, k = i & 31;
        sWih[k * WPAD + g] = Wih[i];
        sWhh[k * WPAD + g] = Whh[i];
    }
    // combined bias, per lane (gate rows lane, 32+lane, 64+lane, 96+lane)
    float bi = bih[lane]          + bhh[lane];
    float bf = bih[HDIM + lane]   + bhh[HDIM + lane];
    float bg = bih[2*HDIM + lane] + bhh[2*HDIM + lane];
    float bo = bih[3*HDIM + lane] + bhh[3*HDIM + lane];
    __syncthreads();

    const int r0 = blockIdx.x * ROWS_PER_CTA + w * EPW;
    float* sMw = sM + (size_t)w * EPW * HDIM;
    const bool full = (r0 + EPW) <= n;

    // ---- load x rows for this warp into sMw ----
    if (full) {
        const float4* gx = reinterpret_cast<const float4*>(x + (size_t)r0 * HDIM);
        float4 v0 = gx[lane], v1 = gx[lane + 32];
        reinterpret_cast<float4*>(sMw)[lane]      = v0;
        reinterpret_cast<float4*>(sMw)[lane + 32] = v1;
    } else {
        #pragma unroll
        for (int e = 0; e < EPW; e++) {
            int r = r0 + e;
            sMw[e * HDIM + lane] = (r < n) ? x[(size_t)r * HDIM + lane] : 0.0f;
        }
    }
    __syncwarp();

    // ---- x_gates = b + x @ W_ih^T  (computed once, kept in regs) ----
    float xi[EPW], xf[EPW], xg[EPW], xo[EPW];
    #pragma unroll
    for (int e = 0; e < EPW; e++) { xi[e] = bi; xf[e] = bf; xg[e] = bg; xo[e] = bo; }
    gate_pass(sWih, sMw, lane, xi, xf, xg, xo);
    __syncwarp();   // done reading x from sMw

    // ---- load h0 into sMw, c0 into regs ----
    if (full) {
        const float4* gh = reinterpret_cast<const float4*>(h0 + (size_t)r0 * HDIM);
        float4 v0 = gh[lane], v1 = gh[lane + 32];
        reinterpret_cast<float4*>(sMw)[lane]      = v0;
        reinterpret_cast<float4*>(sMw)[lane + 32] = v1;
    } else {
        #pragma unroll
        for (int e = 0; e < EPW; e++) {
            int r = r0 + e;
            sMw[e * HDIM + lane] = (r < n) ? h0[(size_t)r * HDIM + lane] : 0.0f;
        }
    }
    float c[EPW];
    #pragma unroll
    for (int e = 0; e < EPW; e++) {
        int r = r0 + e;
        c[e] = (r < n) ? c0[(size_t)r * HDIM + lane] : 0.0f;
    }
    __syncwarp();

    // ---- 4 recurrent steps ----
    float hreg[EPW];
    for (int s = 0; s < 4; s++) {
        float ai[EPW], af[EPW], ag[EPW], ao[EPW];
        #pragma unroll
        for (int e = 0; e < EPW; e++) { ai[e] = xi[e]; af[e] = xf[e]; ag[e] = xg[e]; ao[e] = xo[e]; }

        gate_pass(sWhh, sMw, lane, ai, af, ag, ao);
        __syncwarp();   // all lanes done reading old h before overwriting

        #pragma unroll
        for (int e = 0; e < EPW; e++) {
            float ig = sigm_f(ai[e]);
            float fg = sigm_f(af[e]);
            float gg = tanh_f(ag[e]);
            float og = sigm_f(ao[e]);
            float cn = fmaf(fg, c[e], ig * gg);
            c[e] = cn;
            float hh = og * tanh_f(cn);
            hh = (hh >= 0.0f) ? hh : NEG_SLOPE * hh;   // LeakyReLU, carried into next step
            hreg[e] = hh;
            sMw[e * HDIM + lane] = hh;
        }
        __syncwarp();   // new h visible before next step's reads
    }

    // ---- store final h ----
    #pragma unroll
    for (int e = 0; e < EPW; e++) {
        int r = r0 + e;
        if (r < n) out[(size_t)r * HDIM + lane] = hreg[e];
    }
}

extern "C" void kernel_launch(void* const* d_in, const int* in_sizes, int n_in,
                              void* d_out, int out_size)
{
    const float* x   = (const float*)d_in[0];   // token_embedding [B,32]
    const float* h0  = (const float*)d_in[1];   // hx0 [B,32]
    const float* c0  = (const float*)d_in[2];   // cx0 [B,32]
    const float* Wih = (const float*)d_in[3];   // [128,32]
    const float* Whh = (const float*)d_in[4];   // [128,32]
    const float* bih = (const float*)d_in[5];   // [128]
    const float* bhh = (const float*)d_in[6];   // [128]
    float* out = (float*)d_out;

    int n = in_sizes[0] / HDIM;                 // batch B
    int grid = (n + ROWS_PER_CTA - 1) / ROWS_PER_CTA;
    lstm4_kernel<<<grid, THREADS>>>(x, h0, c0, Wih, Whh, bih, bhh, out, n);
}

// round 3
// speedup vs baseline: 1.2422x; 1.2422x over previous
#include <cuda_runtime.h>
#include <cstddef>

typedef unsigned long long ull;

#define THREADS 256
#define WARPS   8
#define EPW     8                      // batch elements per warp
#define ROWS_PER_CTA (WARPS * EPW)     // 64
#define HDIM    32
#define NEG_SLOPE 0.01f

// ---- packed f32x2 helpers (sm_100+ packed-FMA; ptxas never auto-fuses) ----
__device__ __forceinline__ ull pack2(float lo, float hi) {
    ull r; asm("mov.b64 %0, {%1, %2};" : "=l"(r) : "f"(lo), "f"(hi)); return r;
}
__device__ __forceinline__ void unpack2(ull v, float& lo, float& hi) {
    asm("mov.b64 {%0, %1}, %2;" : "=f"(lo), "=f"(hi) : "l"(v));
}
__device__ __forceinline__ ull fma2(ull a, ull b, ull c) {
    ull d; asm("fma.rn.f32x2 %0, %1, %2, %3;" : "=l"(d) : "l"(a), "l"(b), "l"(c)); return d;
}

__device__ __forceinline__ float sigm_f(float x) {
    return __fdividef(1.0f, 1.0f + __expf(-x));
}
__device__ __forceinline__ float tanh_f(float x) {
    return __fdividef(2.0f, 1.0f + __expf(-2.0f * x)) - 1.0f;
}

// One packed matvec pass:
//   aif[e] += {Wi[lane][k], Wf[lane][k]} * {m[e][k], m[e][k]}   (and ago with g,o)
// sW2: [k][0..31] = {Wi,Wf} pairs, [k][32..63] = {Wg,Wo} pairs
// sMe: per-warp duplicated source tile, sMe[e*HDIM + k] = {m,m}
__device__ __forceinline__ void gate_pass2(
    const ull* __restrict__ sW2, const ull* __restrict__ sMe, int lane,
    ull (&aif)[EPW], ull (&ago)[EPW])
{
    #pragma unroll
    for (int t = 0; t < HDIM / 2; t++) {          // two k per iteration
        const int k0 = 2 * t;
        ull w_if0 = sW2[(size_t)k0 * 64 + lane];
        ull w_go0 = sW2[(size_t)k0 * 64 + 32 + lane];
        ull w_if1 = sW2[(size_t)(k0 + 1) * 64 + lane];
        ull w_go1 = sW2[(size_t)(k0 + 1) * 64 + 32 + lane];
        #pragma unroll
        for (int e = 0; e < EPW; e++) {
            // broadcast LDS.128: two duplicated m values {m_k0,m_k0},{m_k1,m_k1}
            ulonglong2 m2 = reinterpret_cast<const ulonglong2*>(sMe + (size_t)e * HDIM)[t];
            aif[e] = fma2(w_if0, m2.x, aif[e]);
            ago[e] = fma2(w_go0, m2.x, ago[e]);
            aif[e] = fma2(w_if1, m2.y, aif[e]);
            ago[e] = fma2(w_go1, m2.y, ago[e]);
        }
    }
}

__global__ __launch_bounds__(THREADS, 2)
void lstm4_kernel(const float* __restrict__ x,
                  const float* __restrict__ h0,
                  const float* __restrict__ c0,
                  const float* __restrict__ Wih,
                  const float* __restrict__ Whh,
                  const float* __restrict__ bih,
                  const float* __restrict__ bhh,
                  float* __restrict__ out, int n)
{
    __shared__ ull sWih2[HDIM * 64];              // 16 KB, gate-paired transposed W_ih
    __shared__ ull sWhh2[HDIM * 64];              // 16 KB
    __shared__ ull sMd[WARPS * EPW * HDIM];       // 16 KB, duplicated per-warp source tile

    const int tid  = threadIdx.x;
    const int lane = tid & 31;
    const int w    = tid >> 5;

    // ---- build gate-paired transposed weights in shared ----
    // sW2[k*64 + j]   (j<32):  {W[j][k],    W[j+32][k]}   (i,f pair for unit j)
    // sW2[k*64 + 32+j]:        {W[j+64][k], W[j+96][k]}   (g,o pair for unit j)
    for (int i = tid; i < HDIM * 64; i += THREADS) {
        int k = i >> 6, j = i & 63;
        int rowA = (j < 32) ? j : (j + 32);
        int rowB = rowA + 32;
        sWih2[i] = pack2(Wih[rowA * HDIM + k], Wih[rowB * HDIM + k]);
        sWhh2[i] = pack2(Whh[rowA * HDIM + k], Whh[rowB * HDIM + k]);
    }
    // combined bias, packed per lane
    ull bif = pack2(bih[lane]          + bhh[lane],
                    bih[HDIM + lane]   + bhh[HDIM + lane]);
    ull bgo = pack2(bih[2*HDIM + lane] + bhh[2*HDIM + lane],
                    bih[3*HDIM + lane] + bhh[3*HDIM + lane]);
    __syncthreads();

    const int r0 = blockIdx.x * ROWS_PER_CTA + w * EPW;
    ull* sMe = sMd + (size_t)w * EPW * HDIM;

    // ---- load x rows (duplicated) ----
    #pragma unroll
    for (int e = 0; e < EPW; e++) {
        int r = r0 + e;
        float v = (r < n) ? x[(size_t)r * HDIM + lane] : 0.0f;
        sMe[(size_t)e * HDIM + lane] = pack2(v, v);
    }
    __syncwarp();

    // ---- x_gates = b + x @ W_ih^T (packed, kept in regs) ----
    ull xif[EPW], xgo[EPW];
    #pragma unroll
    for (int e = 0; e < EPW; e++) { xif[e] = bif; xgo[e] = bgo; }
    gate_pass2(sWih2, sMe, lane, xif, xgo);
    __syncwarp();

    // ---- load h0 (duplicated) and c0 (regs) ----
    float c[EPW];
    #pragma unroll
    for (int e = 0; e < EPW; e++) {
        int r = r0 + e;
        float v = (r < n) ? h0[(size_t)r * HDIM + lane] : 0.0f;
        sMe[(size_t)e * HDIM + lane] = pack2(v, v);
        c[e] = (r < n) ? c0[(size_t)r * HDIM + lane] : 0.0f;
    }
    __syncwarp();

    // ---- 4 recurrent steps ----
    float hreg[EPW];
    #pragma unroll
    for (int s = 0; s < 4; s++) {
        ull aif[EPW], ago[EPW];
        #pragma unroll
        for (int e = 0; e < EPW; e++) { aif[e] = xif[e]; ago[e] = xgo[e]; }

        gate_pass2(sWhh2, sMe, lane, aif, ago);
        __syncwarp();   // everyone done reading old h

        #pragma unroll
        for (int e = 0; e < EPW; e++) {
            float ai, af, ag, ao;
            unpack2(aif[e], ai, af);
            unpack2(ago[e], ag, ao);
            float ig = sigm_f(ai);
            float fg = sigm_f(af);
            float gg = tanh_f(ag);
            float og = sigm_f(ao);
            float cn = fmaf(fg, c[e], ig * gg);
            c[e] = cn;
            float hh = og * tanh_f(cn);
            hh = (hh >= 0.0f) ? hh : NEG_SLOPE * hh;  // LeakyReLU each step
            hreg[e] = hh;
            sMe[(size_t)e * HDIM + lane] = pack2(hh, hh);
        }
        __syncwarp();   // new h visible before next pass
    }

    // ---- store final h ----
    #pragma unroll
    for (int e = 0; e < EPW; e++) {
        int r = r0 + e;
        if (r < n) out[(size_t)r * HDIM + lane] = hreg[e];
    }
}

extern "C" void kernel_launch(void* const* d_in, const int* in_sizes, int n_in,
                              void* d_out, int out_size)
{
    const float* x   = (const float*)d_in[0];   // token_embedding [B,32]
    const float* h0  = (const float*)d_in[1];   // hx0 [B,32]
    const float* c0  = (const float*)d_in[2];   // cx0 [B,32]
    const float* Wih = (const float*)d_in[3];   // [128,32]
    const float* Whh = (const float*)d_in[4];   // [128,32]
    const float* bih = (const float*)d_in[5];   // [128]
    const float* bhh = (const float*)d_in[6];   // [128]
    float* out = (float*)d_out;

    int n = in_sizes[0] / HDIM;                 // batch B
    int grid = (n + ROWS_PER_CTA - 1) / ROWS_PER_CTA;
    lstm4_kernel<<<grid, THREADS>>>(x, h0, c0, Wih, Whh, bih, bhh, out, n);
}

// round 5
// speedup vs baseline: 1.2631x; 1.0168x over previous
#include <cuda_runtime.h>
#include <cstddef>

typedef unsigned long long ull;

#define THREADS 256
#define WARPS   8
#define EPW     8                      // batch elements per warp
#define ROWS_PER_CTA (WARPS * EPW)     // 64
#define HDIM    32
#define NEG_SLOPE 0.01f

// ---- packed f32x2 helpers ----
__device__ __forceinline__ ull pack2(float lo, float hi) {
    ull r; asm("mov.b64 %0, {%1, %2};" : "=l"(r) : "f"(lo), "f"(hi)); return r;
}
__device__ __forceinline__ void unpack2(ull v, float& lo, float& hi) {
    asm("mov.b64 {%0, %1}, %2;" : "=f"(lo), "=f"(hi) : "l"(v));
}
__device__ __forceinline__ ull fma2(ull a, ull b, ull c) {
    ull d; asm("fma.rn.f32x2 %0, %1, %2, %3;" : "=l"(d) : "l"(a), "l"(b), "l"(c)); return d;
}

__device__ __forceinline__ float sigm_f(float x) {
    return __fdividef(1.0f, 1.0f + __expf(-x));
}
__device__ __forceinline__ float tanh_f(float x) {
    return __fdividef(2.0f, 1.0f + __expf(-2.0f * x)) - 1.0f;
}

// k-pair packed matvec pass.
// sW (ulonglong2 units), layout [t][p][j], t = k-pair (0..15), p=0:{i,f} p=1:{g,o}, j = lane.
//   sW[t*64 + p*32 + j].x = {W[(2p+0)*32+j][2t], W[(2p+0)*32+j][2t+1]}
//   sW[t*64 + p*32 + j].y = {W[(2p+1)*32+j][2t], W[(2p+1)*32+j][2t+1]}
// sMe: plain per-warp source tile, sMe[e*32 + k] (fp32).
// Accumulators hold {even-k partial, odd-k partial}; reduce with lo+hi later.
__device__ __forceinline__ void gate_pass_kp(
    const ulonglong2* __restrict__ sW, const float* __restrict__ sMe, int lane,
    ull (&ai)[EPW], ull (&af)[EPW], ull (&ag)[EPW], ull (&ao)[EPW])
{
    #pragma unroll
    for (int tt = 0; tt < 8; tt++) {              // k-quad: k = 4tt .. 4tt+3
        ulonglong2 wif0 = sW[(size_t)(2*tt)   * 64 + lane];
        ulonglong2 wgo0 = sW[(size_t)(2*tt)   * 64 + 32 + lane];
        ulonglong2 wif1 = sW[(size_t)(2*tt+1) * 64 + lane];
        ulonglong2 wgo1 = sW[(size_t)(2*tt+1) * 64 + 32 + lane];
        #pragma unroll
        for (int e = 0; e < EPW; e++) {
            // broadcast LDS.128: {h[4tt],h[4tt+1]} and {h[4tt+2],h[4tt+3]} raw-packed
            ulonglong2 m2 = reinterpret_cast<const ulonglong2*>(sMe + (size_t)e * HDIM)[tt];
            ai[e] = fma2(wif0.x, m2.x, ai[e]);
            af[e] = fma2(wif0.y, m2.x, af[e]);
            ag[e] = fma2(wgo0.x, m2.x, ag[e]);
            ao[e] = fma2(wgo0.y, m2.x, ao[e]);
            ai[e] = fma2(wif1.x, m2.y, ai[e]);
            af[e] = fma2(wif1.y, m2.y, af[e]);
            ag[e] = fma2(wgo1.x, m2.y, ag[e]);
            ao[e] = fma2(wgo1.y, m2.y, ao[e]);
        }
    }
}

__global__ __launch_bounds__(THREADS, 2)
void lstm4_kernel(const float* __restrict__ x,
                  const float* __restrict__ h0,
                  const float* __restrict__ c0,
                  const float* __restrict__ Wih,
                  const float* __restrict__ Whh,
                  const float* __restrict__ bih,
                  const float* __restrict__ bhh,
                  float* __restrict__ out, int n)
{
    __shared__ ulonglong2 sWih[16 * 64];                         // 16 KB
    __shared__ ulonglong2 sWhh[16 * 64];                         // 16 KB
    __shared__ __align__(16) float sM[WARPS * EPW * HDIM];       // 8 KB

    const int tid  = threadIdx.x;
    const int lane = tid & 31;
    const int w    = tid >> 5;

    // ---- stage k-pair-packed weights ----
    for (int i = tid; i < 16 * 64; i += THREADS) {
        int t = i >> 6, p = (i >> 5) & 1, j = i & 31;
        int rA = (2 * p)     * HDIM + j;
        int rB = (2 * p + 1) * HDIM + j;
        sWih[i] = make_ulonglong2(
            pack2(Wih[rA * HDIM + 2*t], Wih[rA * HDIM + 2*t + 1]),
            pack2(Wih[rB * HDIM + 2*t], Wih[rB * HDIM + 2*t + 1]));
        sWhh[i] = make_ulonglong2(
            pack2(Whh[rA * HDIM + 2*t], Whh[rA * HDIM + 2*t + 1]),
            pack2(Whh[rB * HDIM + 2*t], Whh[rB * HDIM + 2*t + 1]));
    }
    const float bi = bih[lane]          + bhh[lane];
    const float bf = bih[HDIM + lane]   + bhh[HDIM + lane];
    const float bg = bih[2*HDIM + lane] + bhh[2*HDIM + lane];
    const float bo = bih[3*HDIM + lane] + bhh[3*HDIM + lane];
    __syncthreads();

    const int r0 = blockIdx.x * ROWS_PER_CTA + w * EPW;
    float* sMe = sM + (size_t)w * EPW * HDIM;

    // ---- stage x rows ----
    #pragma unroll
    for (int e = 0; e < EPW; e++) {
        int r = r0 + e;
        sMe[(size_t)e * HDIM + lane] = (r < n) ? x[(size_t)r * HDIM + lane] : 0.0f;
    }
    __syncwarp();

    // ---- x_gates = b + x @ W_ih^T  (reduced to scalars, kept in regs) ----
    float xi[EPW], xf[EPW], xg[EPW], xo[EPW];
    {
        ull ai[EPW], af_[EPW], ag[EPW], ao[EPW];
        #pragma unroll
        for (int e = 0; e < EPW; e++) { ai[e] = 0ull; af_[e] = 0ull; ag[e] = 0ull; ao[e] = 0ull; }
        gate_pass_kp(sWih, sMe, lane, ai, af_, ag, ao);
        #pragma unroll
        for (int e = 0; e < EPW; e++) {
            float lo, hi;
            unpack2(ai[e],  lo, hi); xi[e] = lo + hi + bi;
            unpack2(af_[e], lo, hi); xf[e] = lo + hi + bf;
            unpack2(ag[e],  lo, hi); xg[e] = lo + hi + bg;
            unpack2(ao[e],  lo, hi); xo[e] = lo + hi + bo;
        }
    }
    __syncwarp();

    // ---- stage h0; c0 in regs ----
    float c[EPW];
    #pragma unroll
    for (int e = 0; e < EPW; e++) {
        int r = r0 + e;
        sMe[(size_t)e * HDIM + lane] = (r < n) ? h0[(size_t)r * HDIM + lane] : 0.0f;
        c[e] = (r < n) ? c0[(size_t)r * HDIM + lane] : 0.0f;
    }
    __syncwarp();

    // ---- 4 recurrent steps ----
    float hreg[EPW];
    #pragma unroll
    for (int s = 0; s < 4; s++) {
        ull ai[EPW], af_[EPW], ag[EPW], ao[EPW];
        #pragma unroll
        for (int e = 0; e < EPW; e++) { ai[e] = 0ull; af_[e] = 0ull; ag[e] = 0ull; ao[e] = 0ull; }

        gate_pass_kp(sWhh, sMe, lane, ai, af_, ag, ao);
        __syncwarp();   // all lanes done reading old h

        #pragma unroll
        for (int e = 0; e < EPW; e++) {
            float lo, hi, gi, gf, gg, go;
            unpack2(ai[e],  lo, hi); gi = lo + hi + xi[e];
            unpack2(af_[e], lo, hi); gf = lo + hi + xf[e];
            unpack2(ag[e],  lo, hi); gg = lo + hi + xg[e];
            unpack2(ao[e],  lo, hi); go = lo + hi + xo[e];
            float ig = sigm_f(gi);
            float fg = sigm_f(gf);
            float gt = tanh_f(gg);
            float og = sigm_f(go);
            float cn = fmaf(fg, c[e], ig * gt);
            c[e] = cn;
            float hv = og * tanh_f(cn);
            hv = (hv >= 0.0f) ? hv : NEG_SLOPE * hv;   // LeakyReLU each step
            hreg[e] = hv;
            sMe[(size_t)e * HDIM + lane] = hv;         // plain fp32 store (1 wf per e)
        }
        __syncwarp();   // new h visible before next pass
    }

    // ---- store final h ----
    #pragma unroll
    for (int e = 0; e < EPW; e++) {
        int r = r0 + e;
        if (r < n) out[(size_t)r * HDIM + lane] = hreg[e];
    }
}

extern "C" void kernel_launch(void* const* d_in, const int* in_sizes, int n_in,
                              void* d_out, int out_size)
{
    const float* x   = (const float*)d_in[0];   // token_embedding [B,32]
    const float* h0  = (const float*)d_in[1];   // hx0 [B,32]
    const float* c0  = (const float*)d_in[2];   // cx0 [B,32]
    const float* Wih = (const float*)d_in[3];   // [128,32]
    const float* Whh = (const float*)d_in[4];   // [128,32]
    const float* bih = (const float*)d_in[5];   // [128]
    const float* bhh = (const float*)d_in[6];   // [128]
    float* out = (float*)d_out;

    int n = in_sizes[0] / HDIM;                 // batch B
    int grid = (n + ROWS_PER_CTA - 1) / ROWS_PER_CTA;
    lstm4_kernel<<<grid, THREADS>>>(x, h0, c0, Wih, Whh, bih, bhh, out, n);
}

// round 7
// speedup vs baseline: 1.6489x; 1.3055x over previous
#include <cuda_runtime.h>
#include <cstdint>
#include <cstddef>

typedef unsigned long long ull;

#define NELEM   2097152            // B for this problem (scratch stride)
#define THREADS 256
#define NEG_SLOPE 0.01f

// ---- weights / bias in constant memory (filled by async D2D memcpy each launch) ----
__constant__ ull   cWih[2048];     // [row r][k-pair t] = raw [128][32] floats reinterpreted
__constant__ ull   cWhh[2048];
__constant__ float cB[256];        // bih[128] | bhh[128]

// ---- x_gates scratch: [unit u][elem e] float4 = (gi,gf,gg,go), 1 GB ----
__device__ float4 xg_scratch[(size_t)32 * NELEM];

// ---- packed f32x2 helpers ----
__device__ __forceinline__ void unpack2(ull v, float& lo, float& hi) {
    asm("mov.b64 {%0, %1}, %2;" : "=f"(lo), "=f"(hi) : "l"(v));
}
__device__ __forceinline__ ull fma2(ull a, ull b, ull c) {
    ull d; asm("fma.rn.f32x2 %0, %1, %2, %3;" : "=l"(d) : "l"(a), "l"(b), "l"(c)); return d;
}

__device__ __forceinline__ float sigm_f(float x) {
    return __fdividef(1.0f, 1.0f + __expf(-x));
}
__device__ __forceinline__ float tanh_f(float x) {
    return __fdividef(2.0f, 1.0f + __expf(-2.0f * x)) - 1.0f;
}

__global__ __launch_bounds__(THREADS, 3)
void lstm4_flip(const float* __restrict__ x,
                const float* __restrict__ h0,
                const float* __restrict__ c0,
                float* __restrict__ out, int n)
{
    const int e = blockIdx.x * THREADS + threadIdx.x;   // one batch element per thread
    if (e >= n) return;

    // m[t] = packed {v[2t], v[2t+1]} of the current matvec source vector (x, then h)
    ull m[16];

    // ---- load x row into packed regs ----
    {
        const ulonglong2* xr = (const ulonglong2*)(x + (size_t)e * 32);
        #pragma unroll
        for (int q = 0; q < 8; q++) { ulonglong2 v = xr[q]; m[2*q] = v.x; m[2*q+1] = v.y; }
    }

    // ---- x-pass: xg[u] = bias + x @ Wih^T rows {u, 32+u, 64+u, 96+u} ----
    #pragma unroll 2
    for (int u = 0; u < 32; u++) {
        ull a0 = 0ull, a1 = 0ull, a2 = 0ull, a3 = 0ull;
        #pragma unroll
        for (int t = 0; t < 16; t++) {
            a0 = fma2(cWih[(u      ) * 16 + t], m[t], a0);
            a1 = fma2(cWih[(u +  32) * 16 + t], m[t], a1);
            a2 = fma2(cWih[(u +  64) * 16 + t], m[t], a2);
            a3 = fma2(cWih[(u +  96) * 16 + t], m[t], a3);
        }
        float lo, hi; float4 g;
        unpack2(a0, lo, hi); g.x = lo + hi + cB[u      ] + cB[128 + u      ];
        unpack2(a1, lo, hi); g.y = lo + hi + cB[u +  32] + cB[128 + u +  32];
        unpack2(a2, lo, hi); g.z = lo + hi + cB[u +  64] + cB[128 + u +  64];
        unpack2(a3, lo, hi); g.w = lo + hi + cB[u +  96] + cB[128 + u +  96];
        xg_scratch[(size_t)u * NELEM + e] = g;          // coalesced STG.128
    }

    // ---- load h0 into packed regs, c0 into local ----
    {
        const ulonglong2* hr = (const ulonglong2*)(h0 + (size_t)e * 32);
        #pragma unroll
        for (int q = 0; q < 8; q++) { ulonglong2 v = hr[q]; m[2*q] = v.x; m[2*q+1] = v.y; }
    }
    __align__(16) float cl[32];    // cell state (local mem: runtime-indexed)
    {
        const float4* cr = (const float4*)(c0 + (size_t)e * 32);
        #pragma unroll
        for (int q = 0; q < 8; q++) ((float4*)cl)[q] = cr[q];
    }
    __align__(16) float hn[32];    // next-step h staging (local mem)

    // ---- 4 recurrent steps ----
    for (int s = 0; s < 4; s++) {
        #pragma unroll 2
        for (int u = 0; u < 32; u++) {
            float4 xgc = xg_scratch[(size_t)u * NELEM + e];   // coalesced LDG.128 (L2-hot)
            ull a0 = 0ull, a1 = 0ull, a2 = 0ull, a3 = 0ull;
            #pragma unroll
            for (int t = 0; t < 16; t++) {
                a0 = fma2(cWhh[(u      ) * 16 + t], m[t], a0);
                a1 = fma2(cWhh[(u +  32) * 16 + t], m[t], a1);
                a2 = fma2(cWhh[(u +  64) * 16 + t], m[t], a2);
                a3 = fma2(cWhh[(u +  96) * 16 + t], m[t], a3);
            }
            float lo, hi, gi, gf, gg, go;
            unpack2(a0, lo, hi); gi = lo + hi + xgc.x;
            unpack2(a1, lo, hi); gf = lo + hi + xgc.y;
            unpack2(a2, lo, hi); gg = lo + hi + xgc.z;
            unpack2(a3, lo, hi); go = lo + hi + xgc.w;

            float ig = sigm_f(gi);
            float fg = sigm_f(gf);
            float gt = tanh_f(gg);
            float og = sigm_f(go);
            float cn = fmaf(fg, cl[u], ig * gt);
            cl[u] = cn;
            float hv = og * tanh_f(cn);
            hv = (hv >= 0.0f) ? hv : NEG_SLOPE * hv;          // LeakyReLU each step
            hn[u] = hv;
        }
        if (s < 3) {
            // reload packed h for next step from local staging
            #pragma unroll
            for (int q = 0; q < 8; q++) {
                ulonglong2 v = ((const ulonglong2*)hn)[q];
                m[2*q] = v.x; m[2*q+1] = v.y;
            }
        }
    }

    // ---- store final h ----
    {
        float4* go4 = (float4*)(out + (size_t)e * 32);
        #pragma unroll
        for (int q = 0; q < 8; q++) go4[q] = ((const float4*)hn)[q];
    }
}

extern "C" void kernel_launch(void* const* d_in, const int* in_sizes, int n_in,
                              void* d_out, int out_size)
{
    const float* x   = (const float*)d_in[0];   // token_embedding [B,32]
    const float* h0  = (const float*)d_in[1];   // hx0 [B,32]
    const float* c0  = (const float*)d_in[2];   // cx0 [B,32]
    float* out = (float*)d_out;

    // weights + biases -> constant memory (D2D async, graph-capturable)
    cudaMemcpyToSymbolAsync(cWih, d_in[3], 128 * 32 * sizeof(float), 0,
                            cudaMemcpyDeviceToDevice, 0);
    cudaMemcpyToSymbolAsync(cWhh, d_in[4], 128 * 32 * sizeof(float), 0,
                            cudaMemcpyDeviceToDevice, 0);
    cudaMemcpyToSymbolAsync(cB,   d_in[5], 128 * sizeof(float), 0,
                            cudaMemcpyDeviceToDevice, 0);
    cudaMemcpyToSymbolAsync(cB,   d_in[6], 128 * sizeof(float), 128 * sizeof(float),
                            cudaMemcpyDeviceToDevice, 0);

    int n = in_sizes[0] / 32;                   // batch B
    int grid = (n + THREADS - 1) / THREADS;
    lstm4_flip<<<grid, THREADS>>>(x, h0, c0, out, n);
}

// round 8
// speedup vs baseline: 1.7465x; 1.0592x over previous
#include <cuda_runtime.h>
#include <cstdint>
#include <cstddef>

typedef unsigned long long ull;

#define NELEM   2097152            // B for this problem (scratch stride)
#define THREADS 256
#define NEG_SLOPE 0.01f

// ---- weights / bias in constant memory (filled by async D2D memcpy each launch) ----
// cW2[r*8 + tt] = {pack(W[r][4tt],W[r][4tt+1]), pack(W[r][4tt+2],W[r][4tt+3])}
// == raw row-major [128][32] float data reinterpreted (same bytes).
__constant__ ulonglong2 cWih2[1024];
__constant__ ulonglong2 cWhh2[1024];
__constant__ float      cB[256];   // bih[128] | bhh[128]

// ---- x_gates scratch: [unit u][elem e] float4 = (gi,gf,gg,go) ----
__device__ float4 xg_scratch[(size_t)32 * NELEM];

__device__ __forceinline__ void unpack2(ull v, float& lo, float& hi) {
    asm("mov.b64 {%0, %1}, %2;" : "=f"(lo), "=f"(hi) : "l"(v));
}
__device__ __forceinline__ ull fma2(ull a, ull b, ull c) {
    ull d; asm("fma.rn.f32x2 %0, %1, %2, %3;" : "=l"(d) : "l"(a), "l"(b), "l"(c)); return d;
}
__device__ __forceinline__ float sigm_f(float x) {
    return __fdividef(1.0f, 1.0f + __expf(-x));
}
__device__ __forceinline__ float tanh_f(float x) {
    return __fdividef(2.0f, 1.0f + __expf(-2.0f * x)) - 1.0f;
}

__global__ __launch_bounds__(THREADS, 2)
void lstm4_flip2(const float* __restrict__ x,
                 const float* __restrict__ h0,
                 const float* __restrict__ c0,
                 float* __restrict__ out, int n)
{
    const int half = (n + 1) >> 1;
    const int e0 = blockIdx.x * THREADS + threadIdx.x;
    if (e0 >= half) return;
    const int  e1   = e0 + half;
    const bool has1 = (e1 < n);
    const int  e1r  = has1 ? e1 : e0;      // safe mirror for loads

    ull m0[16], m1[16];                    // packed source vectors for both elements

    // ---- load x rows ----
    {
        const ulonglong2* xr0 = (const ulonglong2*)(x + (size_t)e0 * 32);
        const ulonglong2* xr1 = (const ulonglong2*)(x + (size_t)e1r * 32);
        #pragma unroll
        for (int q = 0; q < 8; q++) {
            ulonglong2 v0 = xr0[q]; m0[2*q] = v0.x; m0[2*q+1] = v0.y;
            ulonglong2 v1 = xr1[q]; m1[2*q] = v1.x; m1[2*q+1] = v1.y;
        }
    }

    // ---- x-pass: xg[u] = bias + x @ Wih^T rows {u, 32+u, 64+u, 96+u} ----
    #pragma unroll 1
    for (int u = 0; u < 32; u++) {
        ull a0=0ull,a1=0ull,a2=0ull,a3=0ull;     // elem0
        ull c0a=0ull,c1a=0ull,c2a=0ull,c3a=0ull; // elem1
        #pragma unroll
        for (int tt = 0; tt < 8; tt++) {
            ulonglong2 w0 = cWih2[(u      ) * 8 + tt];
            ulonglong2 w1 = cWih2[(u +  32) * 8 + tt];
            ulonglong2 w2 = cWih2[(u +  64) * 8 + tt];
            ulonglong2 w3 = cWih2[(u +  96) * 8 + tt];
            a0  = fma2(w0.x, m0[2*tt], a0);  a0  = fma2(w0.y, m0[2*tt+1], a0);
            a1  = fma2(w1.x, m0[2*tt], a1);  a1  = fma2(w1.y, m0[2*tt+1], a1);
            a2  = fma2(w2.x, m0[2*tt], a2);  a2  = fma2(w2.y, m0[2*tt+1], a2);
            a3  = fma2(w3.x, m0[2*tt], a3);  a3  = fma2(w3.y, m0[2*tt+1], a3);
            c0a = fma2(w0.x, m1[2*tt], c0a); c0a = fma2(w0.y, m1[2*tt+1], c0a);
            c1a = fma2(w1.x, m1[2*tt], c1a); c1a = fma2(w1.y, m1[2*tt+1], c1a);
            c2a = fma2(w2.x, m1[2*tt], c2a); c2a = fma2(w2.y, m1[2*tt+1], c2a);
            c3a = fma2(w3.x, m1[2*tt], c3a); c3a = fma2(w3.y, m1[2*tt+1], c3a);
        }
        float bi = cB[u] + cB[128+u];
        float bf = cB[u+32] + cB[128+u+32];
        float bg = cB[u+64] + cB[128+u+64];
        float bo = cB[u+96] + cB[128+u+96];
        float lo, hi; float4 g;
        unpack2(a0, lo, hi); g.x = lo + hi + bi;
        unpack2(a1, lo, hi); g.y = lo + hi + bf;
        unpack2(a2, lo, hi); g.z = lo + hi + bg;
        unpack2(a3, lo, hi); g.w = lo + hi + bo;
        xg_scratch[(size_t)u * NELEM + e0] = g;
        unpack2(c0a, lo, hi); g.x = lo + hi + bi;
        unpack2(c1a, lo, hi); g.y = lo + hi + bf;
        unpack2(c2a, lo, hi); g.z = lo + hi + bg;
        unpack2(c3a, lo, hi); g.w = lo + hi + bo;
        if (has1) xg_scratch[(size_t)u * NELEM + e1] = g;
    }

    // ---- load h0 into packed regs, c0 into local ----
    {
        const ulonglong2* hr0 = (const ulonglong2*)(h0 + (size_t)e0 * 32);
        const ulonglong2* hr1 = (const ulonglong2*)(h0 + (size_t)e1r * 32);
        #pragma unroll
        for (int q = 0; q < 8; q++) {
            ulonglong2 v0 = hr0[q]; m0[2*q] = v0.x; m0[2*q+1] = v0.y;
            ulonglong2 v1 = hr1[q]; m1[2*q] = v1.x; m1[2*q+1] = v1.y;
        }
    }
    __align__(16) float cl0[32], cl1[32], hn0[32], hn1[32];
    {
        const float4* cr0 = (const float4*)(c0 + (size_t)e0 * 32);
        const float4* cr1 = (const float4*)(c0 + (size_t)e1r * 32);
        #pragma unroll
        for (int q = 0; q < 8; q++) {
            ((float4*)cl0)[q] = cr0[q];
            ((float4*)cl1)[q] = cr1[q];
        }
    }

    // ---- 4 recurrent steps ----
    for (int s = 0; s < 4; s++) {
        #pragma unroll 1
        for (int u = 0; u < 32; u++) {
            float4 xga = xg_scratch[(size_t)u * NELEM + e0];
            float4 xgb = xg_scratch[(size_t)u * NELEM + e1r];
            ull a0=0ull,a1=0ull,a2=0ull,a3=0ull;
            ull c0a=0ull,c1a=0ull,c2a=0ull,c3a=0ull;
            #pragma unroll
            for (int tt = 0; tt < 8; tt++) {
                ulonglong2 w0 = cWhh2[(u      ) * 8 + tt];
                ulonglong2 w1 = cWhh2[(u +  32) * 8 + tt];
                ulonglong2 w2 = cWhh2[(u +  64) * 8 + tt];
                ulonglong2 w3 = cWhh2[(u +  96) * 8 + tt];
                a0  = fma2(w0.x, m0[2*tt], a0);  a0  = fma2(w0.y, m0[2*tt+1], a0);
                a1  = fma2(w1.x, m0[2*tt], a1);  a1  = fma2(w1.y, m0[2*tt+1], a1);
                a2  = fma2(w2.x, m0[2*tt], a2);  a2  = fma2(w2.y, m0[2*tt+1], a2);
                a3  = fma2(w3.x, m0[2*tt], a3);  a3  = fma2(w3.y, m0[2*tt+1], a3);
                c0a = fma2(w0.x, m1[2*tt], c0a); c0a = fma2(w0.y, m1[2*tt+1], c0a);
                c1a = fma2(w1.x, m1[2*tt], c1a); c1a = fma2(w1.y, m1[2*tt+1], c1a);
                c2a = fma2(w2.x, m1[2*tt], c2a); c2a = fma2(w2.y, m1[2*tt+1], c2a);
                c3a = fma2(w3.x, m1[2*tt], c3a); c3a = fma2(w3.y, m1[2*tt+1], c3a);
            }
            float lo, hi, gi, gf, gg, go;
            // elem 0
            unpack2(a0, lo, hi); gi = lo + hi + xga.x;
            unpack2(a1, lo, hi); gf = lo + hi + xga.y;
            unpack2(a2, lo, hi); gg = lo + hi + xga.z;
            unpack2(a3, lo, hi); go = lo + hi + xga.w;
            {
                float ig = sigm_f(gi), fg = sigm_f(gf);
                float gt = tanh_f(gg), og = sigm_f(go);
                float cn = fmaf(fg, cl0[u], ig * gt);
                cl0[u] = cn;
                float hv = og * tanh_f(cn);
                hn0[u] = (hv >= 0.0f) ? hv : NEG_SLOPE * hv;
            }
            // elem 1
            unpack2(c0a, lo, hi); gi = lo + hi + xgb.x;
            unpack2(c1a, lo, hi); gf = lo + hi + xgb.y;
            unpack2(c2a, lo, hi); gg = lo + hi + xgb.z;
            unpack2(c3a, lo, hi); go = lo + hi + xgb.w;
            {
                float ig = sigm_f(gi), fg = sigm_f(gf);
                float gt = tanh_f(gg), og = sigm_f(go);
                float cn = fmaf(fg, cl1[u], ig * gt);
                cl1[u] = cn;
                float hv = og * tanh_f(cn);
                hn1[u] = (hv >= 0.0f) ? hv : NEG_SLOPE * hv;
            }
        }
        if (s < 3) {
            #pragma unroll
            for (int q = 0; q < 8; q++) {
                ulonglong2 v0 = ((const ulonglong2*)hn0)[q];
                m0[2*q] = v0.x; m0[2*q+1] = v0.y;
                ulonglong2 v1 = ((const ulonglong2*)hn1)[q];
                m1[2*q] = v1.x; m1[2*q+1] = v1.y;
            }
        }
    }

    // ---- store final h ----
    {
        float4* go0 = (float4*)(out + (size_t)e0 * 32);
        #pragma unroll
        for (int q = 0; q < 8; q++) go0[q] = ((const float4*)hn0)[q];
        if (has1) {
            float4* go1 = (float4*)(out + (size_t)e1 * 32);
            #pragma unroll
            for (int q = 0; q < 8; q++) go1[q] = ((const float4*)hn1)[q];
        }
    }
}

extern "C" void kernel_launch(void* const* d_in, const int* in_sizes, int n_in,
                              void* d_out, int out_size)
{
    const float* x   = (const float*)d_in[0];   // token_embedding [B,32]
    const float* h0  = (const float*)d_in[1];   // hx0 [B,32]
    const float* c0  = (const float*)d_in[2];   // cx0 [B,32]
    float* out = (float*)d_out;

    // weights + biases -> constant memory (D2D async, graph-capturable)
    cudaMemcpyToSymbolAsync(cWih2, d_in[3], 128 * 32 * sizeof(float), 0,
                            cudaMemcpyDeviceToDevice, 0);
    cudaMemcpyToSymbolAsync(cWhh2, d_in[4], 128 * 32 * sizeof(float), 0,
                            cudaMemcpyDeviceToDevice, 0);
    cudaMemcpyToSymbolAsync(cB,    d_in[5], 128 * sizeof(float), 0,
                            cudaMemcpyDeviceToDevice, 0);
    cudaMemcpyToSymbolAsync(cB,    d_in[6], 128 * sizeof(float), 128 * sizeof(float),
                            cudaMemcpyDeviceToDevice, 0);

    int n = in_sizes[0] / 32;                   // batch B
    int half = (n + 1) >> 1;
    int grid = (half + THREADS - 1) / THREADS;
    lstm4_flip2<<<grid, THREADS>>>(x, h0, c0, out, n);
}

// round 10
// speedup vs baseline: 1.7886x; 1.0241x over previous
#include <cuda_runtime.h>
#include <cstdint>
#include <cstddef>

typedef unsigned long long ull;

#define NELEM   2097152            // B for this problem (scratch stride)
#define THREADS 256
#define NEG_SLOPE 0.01f

// ---- weights / bias in constant memory (filled by async D2D memcpy each launch) ----
__constant__ ulonglong2 cWih2[1024];   // raw [128][32] floats reinterpreted as f32x2 pairs
__constant__ ulonglong2 cWhh2[1024];
__constant__ float      cB[256];       // bih[128] | bhh[128]

// ---- x_gates scratch: [unit u][elem e] float4 = (gi,gf,gg,go) ----
__device__ float4 xg_scratch[(size_t)32 * NELEM];

__device__ __forceinline__ void unpack2(ull v, float& lo, float& hi) {
    asm("mov.b64 {%0, %1}, %2;" : "=f"(lo), "=f"(hi) : "l"(v));
}
__device__ __forceinline__ ull fma2(ull a, ull b, ull c) {
    ull d; asm("fma.rn.f32x2 %0, %1, %2, %3;" : "=l"(d) : "l"(a), "l"(b), "l"(c)); return d;
}
__device__ __forceinline__ float sigm_f(float x) {
    return __fdividef(1.0f, 1.0f + __expf(-x));
}
__device__ __forceinline__ float tanh_f(float x) {
    return __fdividef(2.0f, 1.0f + __expf(-2.0f * x)) - 1.0f;
}

// ---- L2 evict_last cache-policy helpers (pin xg_scratch in L2 across steps) ----
__device__ __forceinline__ ull mk_evict_last() {
    ull p; asm("createpolicy.fractional.L2::evict_last.b64 %0, 1.0;" : "=l"(p));
    return p;
}
__device__ __forceinline__ float4 ldg_pol(const float4* a, ull pol) {
    float4 v;
    asm volatile("ld.global.L2::cache_hint.v4.f32 {%0,%1,%2,%3}, [%4], %5;"
                 : "=f"(v.x), "=f"(v.y), "=f"(v.z), "=f"(v.w)
                 : "l"(a), "l"(pol));
    return v;
}
__device__ __forceinline__ void stg_pol(float4* a, float4 v, ull pol) {
    asm volatile("st.global.L2::cache_hint.v4.f32 [%0], {%1,%2,%3,%4}, %5;"
                 :: "l"(a), "f"(v.x), "f"(v.y), "f"(v.z), "f"(v.w), "l"(pol)
                 : "memory");
}

__global__ __launch_bounds__(THREADS, 2)
void lstm4_flip2(const float* __restrict__ x,
                 const float* __restrict__ h0,
                 const float* __restrict__ c0,
                 float* __restrict__ out, int n)
{
    const int half = (n + 1) >> 1;
    const int e0 = blockIdx.x * THREADS + threadIdx.x;
    if (e0 >= half) return;
    const int  e1   = e0 + half;
    const bool has1 = (e1 < n);
    const int  e1r  = has1 ? e1 : e0;      // safe mirror for loads

    const ull pol = mk_evict_last();

    ull m0[16], m1[16];                    // packed source vectors for both elements

    // ---- load x rows (streaming) ----
    {
        const float4* xr0 = (const float4*)(x + (size_t)e0 * 32);
        const float4* xr1 = (const float4*)(x + (size_t)e1r * 32);
        #pragma unroll
        for (int q = 0; q < 4; q++) {
            float4 a = __ldcs(xr0 + 2*q), b = __ldcs(xr0 + 2*q + 1);
            ulonglong2 v; v.x = ((ull*)&a)[0]; v.y = ((ull*)&a)[1];
            m0[4*q] = v.x; m0[4*q+1] = v.y;
            v.x = ((ull*)&b)[0]; v.y = ((ull*)&b)[1];
            m0[4*q+2] = v.x; m0[4*q+3] = v.y;
            a = __ldcs(xr1 + 2*q); b = __ldcs(xr1 + 2*q + 1);
            v.x = ((ull*)&a)[0]; v.y = ((ull*)&a)[1];
            m1[4*q] = v.x; m1[4*q+1] = v.y;
            v.x = ((ull*)&b)[0]; v.y = ((ull*)&b)[1];
            m1[4*q+2] = v.x; m1[4*q+3] = v.y;
        }
    }

    // ---- x-pass: xg[u] = bias + x @ Wih^T rows {u, 32+u, 64+u, 96+u} ----
    #pragma unroll 1
    for (int u = 0; u < 32; u++) {
        ull a0=0ull,a1=0ull,a2=0ull,a3=0ull;     // elem0
        ull c0a=0ull,c1a=0ull,c2a=0ull,c3a=0ull; // elem1
        #pragma unroll
        for (int tt = 0; tt < 8; tt++) {
            ulonglong2 w0 = cWih2[(u      ) * 8 + tt];
            ulonglong2 w1 = cWih2[(u +  32) * 8 + tt];
            ulonglong2 w2 = cWih2[(u +  64) * 8 + tt];
            ulonglong2 w3 = cWih2[(u +  96) * 8 + tt];
            a0  = fma2(w0.x, m0[2*tt], a0);  a0  = fma2(w0.y, m0[2*tt+1], a0);
            a1  = fma2(w1.x, m0[2*tt], a1);  a1  = fma2(w1.y, m0[2*tt+1], a1);
            a2  = fma2(w2.x, m0[2*tt], a2);  a2  = fma2(w2.y, m0[2*tt+1], a2);
            a3  = fma2(w3.x, m0[2*tt], a3);  a3  = fma2(w3.y, m0[2*tt+1], a3);
            c0a = fma2(w0.x, m1[2*tt], c0a); c0a = fma2(w0.y, m1[2*tt+1], c0a);
            c1a = fma2(w1.x, m1[2*tt], c1a); c1a = fma2(w1.y, m1[2*tt+1], c1a);
            c2a = fma2(w2.x, m1[2*tt], c2a); c2a = fma2(w2.y, m1[2*tt+1], c2a);
            c3a = fma2(w3.x, m1[2*tt], c3a); c3a = fma2(w3.y, m1[2*tt+1], c3a);
        }
        float bi = cB[u] + cB[128+u];
        float bf = cB[u+32] + cB[128+u+32];
        float bg = cB[u+64] + cB[128+u+64];
        float bo = cB[u+96] + cB[128+u+96];
        float lo, hi; float4 g;
        unpack2(a0, lo, hi); g.x = lo + hi + bi;
        unpack2(a1, lo, hi); g.y = lo + hi + bf;
        unpack2(a2, lo, hi); g.z = lo + hi + bg;
        unpack2(a3, lo, hi); g.w = lo + hi + bo;
        stg_pol(&xg_scratch[(size_t)u * NELEM + e0], g, pol);
        unpack2(c0a, lo, hi); g.x = lo + hi + bi;
        unpack2(c1a, lo, hi); g.y = lo + hi + bf;
        unpack2(c2a, lo, hi); g.z = lo + hi + bg;
        unpack2(c3a, lo, hi); g.w = lo + hi + bo;
        if (has1) stg_pol(&xg_scratch[(size_t)u * NELEM + e1], g, pol);
    }

    // ---- load h0 into packed regs (streaming), c0 into local ----
    {
        const float4* hr0 = (const float4*)(h0 + (size_t)e0 * 32);
        const float4* hr1 = (const float4*)(h0 + (size_t)e1r * 32);
        #pragma unroll
        for (int q = 0; q < 4; q++) {
            float4 a = __ldcs(hr0 + 2*q), b = __ldcs(hr0 + 2*q + 1);
            m0[4*q]   = ((ull*)&a)[0]; m0[4*q+1] = ((ull*)&a)[1];
            m0[4*q+2] = ((ull*)&b)[0]; m0[4*q+3] = ((ull*)&b)[1];
            a = __ldcs(hr1 + 2*q); b = __ldcs(hr1 + 2*q + 1);
            m1[4*q]   = ((ull*)&a)[0]; m1[4*q+1] = ((ull*)&a)[1];
            m1[4*q+2] = ((ull*)&b)[0]; m1[4*q+3] = ((ull*)&b)[1];
        }
    }
    __align__(16) float cl0[32], cl1[32], hn0[32], hn1[32];
    {
        const float4* cr0 = (const float4*)(c0 + (size_t)e0 * 32);
        const float4* cr1 = (const float4*)(c0 + (size_t)e1r * 32);
        #pragma unroll
        for (int q = 0; q < 8; q++) {
            ((float4*)cl0)[q] = __ldcs(cr0 + q);
            ((float4*)cl1)[q] = __ldcs(cr1 + q);
        }
    }

    // ---- 4 recurrent steps ----
    for (int s = 0; s < 4; s++) {
        // prefetch-pipelined xg reads (L2-pinned)
        float4 xga = ldg_pol(&xg_scratch[(size_t)0 * NELEM + e0], pol);
        float4 xgb = ldg_pol(&xg_scratch[(size_t)0 * NELEM + e1r], pol);
        #pragma unroll 1
        for (int u = 0; u < 32; u++) {
            float4 nxga, nxgb;
            if (u < 31) {
                nxga = ldg_pol(&xg_scratch[(size_t)(u+1) * NELEM + e0], pol);
                nxgb = ldg_pol(&xg_scratch[(size_t)(u+1) * NELEM + e1r], pol);
            }
            ull a0=0ull,a1=0ull,a2=0ull,a3=0ull;
            ull c0a=0ull,c1a=0ull,c2a=0ull,c3a=0ull;
            #pragma unroll
            for (int tt = 0; tt < 8; tt++) {
                ulonglong2 w0 = cWhh2[(u      ) * 8 + tt];
                ulonglong2 w1 = cWhh2[(u +  32) * 8 + tt];
                ulonglong2 w2 = cWhh2[(u +  64) * 8 + tt];
                ulonglong2 w3 = cWhh2[(u +  96) * 8 + tt];
                a0  = fma2(w0.x, m0[2*tt], a0);  a0  = fma2(w0.y, m0[2*tt+1], a0);
                a1  = fma2(w1.x, m0[2*tt], a1);  a1  = fma2(w1.y, m0[2*tt+1], a1);
                a2  = fma2(w2.x, m0[2*tt], a2);  a2  = fma2(w2.y, m0[2*tt+1], a2);
                a3  = fma2(w3.x, m0[2*tt], a3);  a3  = fma2(w3.y, m0[2*tt+1], a3);
                c0a = fma2(w0.x, m1[2*tt], c0a); c0a = fma2(w0.y, m1[2*tt+1], c0a);
                c1a = fma2(w1.x, m1[2*tt], c1a); c1a = fma2(w1.y, m1[2*tt+1], c1a);
                c2a = fma2(w2.x, m1[2*tt], c2a); c2a = fma2(w2.y, m1[2*tt+1], c2a);
                c3a = fma2(w3.x, m1[2*tt], c3a); c3a = fma2(w3.y, m1[2*tt+1], c3a);
            }
            float lo, hi, gi, gf, gg, go;
            // elem 0
            unpack2(a0, lo, hi); gi = lo + hi + xga.x;
            unpack2(a1, lo, hi); gf = lo + hi + xga.y;
            unpack2(a2, lo, hi); gg = lo + hi + xga.z;
            unpack2(a3, lo, hi); go = lo + hi + xga.w;
            {
                float ig = sigm_f(gi), fg = sigm_f(gf);
                float gt = tanh_f(gg), og = sigm_f(go);
                float cn = fmaf(fg, cl0[u], ig * gt);
                cl0[u] = cn;
                float hv = og * tanh_f(cn);
                hn0[u] = (hv >= 0.0f) ? hv : NEG_SLOPE * hv;
            }
            // elem 1
            unpack2(c0a, lo, hi); gi = lo + hi + xgb.x;
            unpack2(c1a, lo, hi); gf = lo + hi + xgb.y;
            unpack2(c2a, lo, hi); gg = lo + hi + xgb.z;
            unpack2(c3a, lo, hi); go = lo + hi + xgb.w;
            {
                float ig = sigm_f(gi), fg = sigm_f(gf);
                float gt = tanh_f(gg), og = sigm_f(go);
                float cn = fmaf(fg, cl1[u], ig * gt);
                cl1[u] = cn;
                float hv = og * tanh_f(cn);
                hn1[u] = (hv >= 0.0f) ? hv : NEG_SLOPE * hv;
            }
            xga = nxga; xgb = nxgb;
        }
        if (s < 3) {
            #pragma unroll
            for (int q = 0; q < 8; q++) {
                ulonglong2 v0 = ((const ulonglong2*)hn0)[q];
                m0[2*q] = v0.x; m0[2*q+1] = v0.y;
                ulonglong2 v1 = ((const ulonglong2*)hn1)[q];
                m1[2*q] = v1.x; m1[2*q+1] = v1.y;
            }
        }
    }

    // ---- store final h (streaming) ----
    {
        float4* go0 = (float4*)(out + (size_t)e0 * 32);
        #pragma unroll
        for (int q = 0; q < 8; q++) __stcs(go0 + q, ((const float4*)hn0)[q]);
        if (has1) {
            float4* go1 = (float4*)(out + (size_t)e1 * 32);
            #pragma unroll
            for (int q = 0; q < 8; q++) __stcs(go1 + q, ((const float4*)hn1)[q]);
        }
    }
}

extern "C" void kernel_launch(void* const* d_in, const int* in_sizes, int n_in,
                              void* d_out, int out_size)
{
    const float* x   = (const float*)d_in[0];   // token_embedding [B,32]
    const float* h0  = (const float*)d_in[1];   // hx0 [B,32]
    const float* c0  = (const float*)d_in[2];   // cx0 [B,32]
    float* out = (float*)d_out;

    // weights + biases -> constant memory (D2D async, graph-capturable)
    cudaMemcpyToSymbolAsync(cWih2, d_in[3], 128 * 32 * sizeof(float), 0,
                            cudaMemcpyDeviceToDevice, 0);
    cudaMemcpyToSymbolAsync(cWhh2, d_in[4], 128 * 32 * sizeof(float), 0,
                            cudaMemcpyDeviceToDevice, 0);
    cudaMemcpyToSymbolAsync(cB,    d_in[5], 128 * sizeof(float), 0,
                            cudaMemcpyDeviceToDevice, 0);
    cudaMemcpyToSymbolAsync(cB,    d_in[6], 128 * sizeof(float), 128 * sizeof(float),
                            cudaMemcpyDeviceToDevice, 0);

    int n = in_sizes[0] / 32;                   // batch B
    int half = (n + 1) >> 1;
    int grid = (half + THREADS - 1) / THREADS;
    lstm4_flip2<<<grid, THREADS>>>(x, h0, c0, out, n);
}